// round 7
// baseline (speedup 1.0000x reference)
#include <cuda_runtime.h>
#include <cuda_bf16.h>
#include <math.h>

// Problem constants
#define NN 4096
#define TT 32
#define DD 158
#define NEWS 1024
#define DGRU 128
#define GG 8
#define EE 8
#define HH 4
#define HID 64          // G*E
#define XDIM 1182       // D + NEWS
#define XPAD 1184       // padded to multiple of 32

// Output layout (float32, concat of tuple)
#define OFF_PRED  0
#define OFF_RW1   4096
#define OFF_HID   266240     // 4096 + 4096*64
#define OFF_TOPK  528384     // + 4096*64
#define OFF_RW2   536576     // + 4096*2

// Pipeline chunking
#define NCH 4
#define CH  (NN / NCH)       // 1024 stocks per chunk

// Scratch buffers
__device__ float g_xbuf[(size_t)NN * XPAD];     // aggregated features [N][XPAD]
__device__ float g_Wt[(size_t)DGRU * XPAD];     // router_W transposed [col][k], zero-padded
__device__ float g_hid[(size_t)NN * DGRU];      // tanh(router) output

// packed fp32x2 FMA (even/odd-k partial sums)
__device__ __forceinline__ void fma2(unsigned long long &d,
                                     unsigned long long a,
                                     unsigned long long b) {
    asm("fma.rn.f32x2 %0, %1, %2, %0;" : "+l"(d) : "l"(a), "l"(b));
}

// ---------------------------------------------------------------------------
// Kernel 1: per-stock aggregation (HBM-bound streaming) + W transpose
// ---------------------------------------------------------------------------
__global__ void __launch_bounds__(256) agg_kernel(
    const float* __restrict__ price,   // [N,T,D]
    const float* __restrict__ news,    // [N,T,NEWS]
    const float* __restrict__ mask,    // [N,T]
    const float* __restrict__ router_W, // [1182,128]
    int n0)
{
    const int n = n0 + blockIdx.x;
    const int tid = threadIdx.x;
    __shared__ float sm[TT];
    __shared__ float sdenom;

    // W transpose side job (first 128 blocks of chunk 0)
    if (n < DGRU) {
        for (int k = tid; k < XPAD; k += 256) {
            g_Wt[(size_t)n * XPAD + k] =
                (k < XDIM) ? router_W[(size_t)k * DGRU + n] : 0.f;
        }
    }

    if (tid < TT) {
        float mv = mask[(size_t)n * TT + tid];
        sm[tid] = mv;
        float s = mv;
        #pragma unroll
        for (int o = 16; o > 0; o >>= 1) s += __shfl_xor_sync(0xffffffffu, s, o);
        if (tid == 0) sdenom = fmaxf(s, 1e-6f);
    }
    __syncthreads();
    const float inv_denom = 1.0f / sdenom;

    // news: each thread owns 4 contiguous dims (one float4)
    const float4* news4 = (const float4*)(news + (size_t)n * TT * NEWS);
    float4 acc = make_float4(0.f, 0.f, 0.f, 0.f);
    #pragma unroll 8
    for (int t = 0; t < TT; t++) {
        float4 v = news4[t * (NEWS / 4) + tid];
        float mt = sm[t];
        acc.x += mt * v.x; acc.y += mt * v.y;
        acc.z += mt * v.z; acc.w += mt * v.w;
    }
    float* xb = g_xbuf + (size_t)n * XPAD;
    xb[DD + 4 * tid + 0] = acc.x * inv_denom;
    xb[DD + 4 * tid + 1] = acc.y * inv_denom;
    xb[DD + 4 * tid + 2] = acc.z * inv_denom;
    xb[DD + 4 * tid + 3] = acc.w * inv_denom;

    // price
    if (tid < DD) {
        float a = 0.f;
        const float* p = price + (size_t)n * TT * DD + tid;
        #pragma unroll 8
        for (int t = 0; t < TT; t++) a += p[t * DD];
        xb[tid] = a * (1.0f / TT);
    }
    if (tid == DD) { xb[XDIM] = 0.f; xb[XDIM + 1] = 0.f; }
}

// ---------------------------------------------------------------------------
// Kernel 2: router GEMM  g_hid = tanh(X @ W + b)   (proven R3 version)
// grid per chunk = (CH/32)*2 blocks, 256 threads.
// Block: 32 stocks x 64 cols, K = 1184 in chunks of 32.
// Thread: 4 stocks x 2 cols, f32x2 accumulators (even/odd-k partials).
// ---------------------------------------------------------------------------
#define SB2 32
#define CB  64
#define KC2 32
#define XSTR 36    // padded smem row stride (floats)

__global__ void __launch_bounds__(256) router_kernel(
    const float* __restrict__ router_b, int s0base)
{
    const int bs = blockIdx.x >> 1;
    const int bc = blockIdx.x & 1;
    const int s0 = s0base + bs * SB2;
    const int c0 = bc * CB;
    const int tid = threadIdx.x;

    __shared__ float Xs[SB2 * XSTR];   // [stock][k]
    __shared__ float Ws[CB  * XSTR];   // [col][k]

    const int sg = tid >> 5;           // warp id = stock group (4 stocks)
    const int cg = tid & 31;           // lane = col group {cg, cg+32}

    // staging indices (thread loads 1 X float4 + 2 W float4 per chunk)
    const int sA = tid >> 3;           // 0..31
    const int kA = (tid & 7) * 4;      // 0..28
    const float* xsrc = g_xbuf + (size_t)(s0 + sA) * XPAD + kA;
    const float* wsrc0 = g_Wt + (size_t)(c0 + sA) * XPAD + kA;
    const float* wsrc1 = g_Wt + (size_t)(c0 + 32 + sA) * XPAD + kA;

    unsigned long long acc[4][2];
    #pragma unroll
    for (int i = 0; i < 4; i++) { acc[i][0] = 0ull; acc[i][1] = 0ull; }

    float4 px  = *(const float4*)(xsrc);
    float4 pw0 = *(const float4*)(wsrc0);
    float4 pw1 = *(const float4*)(wsrc1);

    for (int kc = 0; kc < XPAD; kc += KC2) {
        *(float4*)&Xs[sA * XSTR + kA]        = px;
        *(float4*)&Ws[sA * XSTR + kA]        = pw0;
        *(float4*)&Ws[(32 + sA) * XSTR + kA] = pw1;
        __syncthreads();

        int kn = kc + KC2;
        if (kn < XPAD) {
            px  = *(const float4*)(xsrc  + kn);
            pw0 = *(const float4*)(wsrc0 + kn);
            pw1 = *(const float4*)(wsrc1 + kn);
        }

        #pragma unroll
        for (int kk = 0; kk < KC2; kk += 4) {
            ulonglong2 w0 = *(ulonglong2*)&Ws[cg * XSTR + kk];
            ulonglong2 w1 = *(ulonglong2*)&Ws[(cg + 32) * XSTR + kk];
            #pragma unroll
            for (int i = 0; i < 4; i++) {
                ulonglong2 x = *(ulonglong2*)&Xs[(sg * 4 + i) * XSTR + kk];
                fma2(acc[i][0], x.x, w0.x);
                fma2(acc[i][0], x.y, w0.y);
                fma2(acc[i][1], x.x, w1.x);
                fma2(acc[i][1], x.y, w1.y);
            }
        }
        __syncthreads();
    }

    // epilogue: combine even/odd partials, bias, tanh, write
    const float b0 = router_b[c0 + cg];
    const float b1 = router_b[c0 + cg + 32];
    #pragma unroll
    for (int i = 0; i < 4; i++) {
        const int s = s0 + sg * 4 + i;
        float v0 = __uint_as_float((unsigned)acc[i][0]) +
                   __uint_as_float((unsigned)(acc[i][0] >> 32)) + b0;
        float v1 = __uint_as_float((unsigned)acc[i][1]) +
                   __uint_as_float((unsigned)(acc[i][1] >> 32)) + b1;
        g_hid[(size_t)s * DGRU + c0 + cg]      = tanhf(v0);
        g_hid[(size_t)s * DGRU + c0 + cg + 32] = tanhf(v1);
    }
}

// ---------------------------------------------------------------------------
// Kernel 3: gate + top2/softmax + expert/attention + outputs (R3 version)
// grid per chunk = CH/16 blocks, 16 stocks per block, 256 threads.
// ---------------------------------------------------------------------------
#define SB3 16
#define HSTR 132   // padded Hs row stride

__global__ void __launch_bounds__(256) tail_kernel(
    const float* __restrict__ gate_W,    // [128,64]
    const float* __restrict__ gate_b,    // [64]
    const float* __restrict__ expert_W,  // [8,8,64]
    const float* __restrict__ expert_b,  // [8,8]
    const float* __restrict__ wq, const float* __restrict__ wq_b,
    const float* __restrict__ wk, const float* __restrict__ wk_b,
    const float* __restrict__ wv, const float* __restrict__ wv_b,
    const float* __restrict__ wo, const float* __restrict__ wo_b,
    float* __restrict__ out, int s0base)
{
    const int s0 = s0base + blockIdx.x * SB3;
    const int tid = threadIdx.x;

    __shared__ float Hs[SB3 * HSTR];   // tanh(router) rows, padded
    __shared__ float Hid[SB3 * HID];
    __shared__ float Out[SB3 * HID];
    __shared__ int   Si1[SB3], Si2[SB3];
    __shared__ float Sw1[SB3], Sw2[SB3];

    // load Hs: 16 x 128 floats = 512 float4, 2 per thread
    #pragma unroll
    for (int i = 0; i < 2; i++) {
        int idx = i * 256 + tid;
        int s = idx >> 5, kq = (idx & 31) * 4;
        *(float4*)&Hs[s * HSTR + kq] =
            *(const float4*)&g_hid[(size_t)(s0 + s) * DGRU + kq];
    }
    __syncthreads();

    // Gate: thread = (stock tid>>4, 4 cols)
    {
        int s  = tid >> 4;
        int cgp = tid & 15;
        float ga0 = gate_b[cgp * 4 + 0];
        float ga1 = gate_b[cgp * 4 + 1];
        float ga2 = gate_b[cgp * 4 + 2];
        float ga3 = gate_b[cgp * 4 + 3];
        #pragma unroll 8
        for (int j = 0; j < DGRU; j++) {
            float hv = Hs[s * HSTR + j];
            float4 w = __ldg((const float4*)&gate_W[j * HID + cgp * 4]);
            ga0 += hv * w.x; ga1 += hv * w.y; ga2 += hv * w.z; ga3 += hv * w.w;
        }
        Hid[s * HID + cgp * 4 + 0] = ga0;
        Hid[s * HID + cgp * 4 + 1] = ga1;
        Hid[s * HID + cgp * 4 + 2] = ga2;
        Hid[s * HID + cgp * 4 + 3] = ga3;
    }
    __syncthreads();

    // Top-2 + softmax, thread per stock
    if (tid < SB3) {
        int s = tid;
        float best1 = -3.4e38f; int i1 = 0;
        for (int c = 0; c < HID; c++) {
            float v = Hid[s * HID + c];
            if (v > best1) { best1 = v; i1 = c; }
        }
        float best2 = -3.4e38f; int i2 = 0;
        for (int c = 0; c < HID; c++) {
            if (c == i1) continue;
            float v = Hid[s * HID + c];
            if (v > best2) { best2 = v; i2 = c; }
        }
        float e2 = expf(best2 - best1);
        float r = 1.0f / (1.0f + e2);
        Si1[s] = i1; Si2[s] = i2;
        Sw1[s] = r;  Sw2[s] = e2 * r;
    }

    // Expert + attention: thread = (stock, group), 128 active threads
    if (tid < SB3 * GG) {
        int s = tid >> 3;
        int g = tid & 7;
        float eo[EE];
        #pragma unroll
        for (int e = 0; e < EE; e++) {
            float a = expert_b[g * EE + e];
            const float4* wr = (const float4*)&expert_W[((size_t)(g * EE + e)) * HID];
            const float4* hr = (const float4*)&Hid[s * HID];
            #pragma unroll
            for (int h4 = 0; h4 < HID / 4; h4++) {
                float4 w = wr[h4];
                float4 h = hr[h4];
                a += w.x * h.x + w.y * h.y + w.z * h.z + w.w * h.w;
            }
            eo[e] = a;
        }
        float q[EE], k[EE], v[EE];
        #pragma unroll
        for (int f = 0; f < EE; f++) {
            float aq = wq_b[g * EE + f];
            float ak = wk_b[g * EE + f];
            float av = wv_b[g * EE + f];
            #pragma unroll
            for (int e = 0; e < EE; e++) {
                aq += eo[e] * wq[(g * EE + f) * EE + e];
                ak += eo[e] * wk[(g * EE + f) * EE + e];
                av += eo[e] * wv[(g * EE + f) * EE + e];
            }
            q[f] = aq; k[f] = ak; v[f] = av;
        }
        const float isq = 0.70710678118654752f;
        float att[EE];
        #pragma unroll
        for (int d = 0; d < 2; d++) {
            float sc0 = 0.f, sc1 = 0.f;
            #pragma unroll
            for (int h = 0; h < HH; h++) {
                float qv = q[h * 2 + d];
                sc0 += qv * k[h * 2 + 0];
                sc1 += qv * k[h * 2 + 1];
            }
            sc0 *= isq; sc1 *= isq;
            float mx = fmaxf(sc0, sc1);
            float p0 = expf(sc0 - mx), p1 = expf(sc1 - mx);
            float rn = 1.0f / (p0 + p1);
            p0 *= rn; p1 *= rn;
            #pragma unroll
            for (int h = 0; h < HH; h++)
                att[h * 2 + d] = p0 * v[h * 2 + 0] + p1 * v[h * 2 + 1];
        }
        #pragma unroll
        for (int f = 0; f < EE; f++) {
            float a = wo_b[g * EE + f];
            #pragma unroll
            for (int e = 0; e < EE; e++)
                a += att[e] * wo[(g * EE + f) * EE + e];
            Out[s * HID + g * EE + f] = a;
        }
    }
    __syncthreads();

    // predictions + topk
    if (tid < SB3) {
        int s = tid;
        int i1 = Si1[s], i2 = Si2[s];
        float pred = Sw1[s] * Out[s * HID + i1] + Sw2[s] * Out[s * HID + i2];
        out[OFF_PRED + s0 + s] = pred;
        out[OFF_TOPK + (size_t)(s0 + s) * 2 + 0] = (float)i1;
        out[OFF_TOPK + (size_t)(s0 + s) * 2 + 1] = (float)i2;
    }

    // hidden + routing_weights (x2): 16 stocks x 64 cols = 256 float4
    {
        int s  = tid >> 4;
        int c  = (tid & 15) * 4;
        float4 hv = *(float4*)&Hid[s * HID + c];
        *(float4*)&out[OFF_HID + (size_t)(s0 + s) * HID + c] = hv;

        int i1 = Si1[s], i2 = Si2[s];
        float w1 = Sw1[s], w2 = Sw2[s];
        float4 rw;
        rw.x = (c + 0 == i1) ? w1 : (c + 0 == i2) ? w2 : 0.f;
        rw.y = (c + 1 == i1) ? w1 : (c + 1 == i2) ? w2 : 0.f;
        rw.z = (c + 2 == i1) ? w1 : (c + 2 == i2) ? w2 : 0.f;
        rw.w = (c + 3 == i1) ? w1 : (c + 3 == i2) ? w2 : 0.f;
        *(float4*)&out[OFF_RW1 + (size_t)(s0 + s) * HID + c] = rw;
        *(float4*)&out[OFF_RW2 + (size_t)(s0 + s) * HID + c] = rw;
    }
}

// ---------------------------------------------------------------------------
extern "C" void kernel_launch(void* const* d_in, const int* in_sizes, int n_in,
                              void* d_out, int out_size) {
    const float* price    = (const float*)d_in[0];
    const float* news     = (const float*)d_in[1];
    const float* mask     = (const float*)d_in[2];
    const float* router_W = (const float*)d_in[3];
    const float* router_b = (const float*)d_in[4];
    const float* gate_W   = (const float*)d_in[5];
    const float* gate_b   = (const float*)d_in[6];
    const float* expert_W = (const float*)d_in[7];
    const float* expert_b = (const float*)d_in[8];
    const float* wq   = (const float*)d_in[9];
    const float* wq_b = (const float*)d_in[10];
    const float* wk   = (const float*)d_in[11];
    const float* wk_b = (const float*)d_in[12];
    const float* wv   = (const float*)d_in[13];
    const float* wv_b = (const float*)d_in[14];
    const float* wo   = (const float*)d_in[15];
    const float* wo_b = (const float*)d_in[16];
    float* out = (float*)d_out;

    // Side stream + events, created once on the (uncaptured) correctness call.
    static cudaStream_t s1 = nullptr;
    static cudaEvent_t evA[NCH];
    static cudaEvent_t evJoin;
    if (s1 == nullptr) {
        cudaStreamCreateWithFlags(&s1, cudaStreamNonBlocking);
        for (int c = 0; c < NCH; c++)
            cudaEventCreateWithFlags(&evA[c], cudaEventDisableTiming);
        cudaEventCreateWithFlags(&evJoin, cudaEventDisableTiming);
    }

    // Pipelined: agg(c) on capture stream; router(c)+tail(c) on s1 after evA[c].
    for (int c = 0; c < NCH; c++) {
        agg_kernel<<<CH, 256>>>(price, news, mask, router_W, c * CH);
        cudaEventRecord(evA[c], 0);
        cudaStreamWaitEvent(s1, evA[c], 0);
        router_kernel<<<(CH / SB2) * 2, 256, 0, s1>>>(router_b, c * CH);
        tail_kernel<<<CH / SB3, 256, 0, s1>>>(gate_W, gate_b, expert_W, expert_b,
                                              wq, wq_b, wk, wk_b, wv, wv_b,
                                              wo, wo_b, out, c * CH);
    }
    cudaEventRecord(evJoin, s1);
    cudaStreamWaitEvent(0, evJoin, 0);
}

// round 10
// speedup vs baseline: 1.8463x; 1.8463x over previous
#include <cuda_runtime.h>
#include <cuda_bf16.h>
#include <math.h>

// Problem constants
#define NN 4096
#define TT 32
#define DD 158
#define NEWS 1024
#define DGRU 128
#define GG 8
#define EE 8
#define HH 4
#define HID 64          // G*E
#define XDIM 1182       // D + NEWS
#define XPAD 1184       // padded to multiple of 32

// Output layout (float32, concat of tuple)
#define OFF_PRED  0
#define OFF_RW1   4096
#define OFF_HID   266240     // 4096 + 4096*64
#define OFF_TOPK  528384     // + 4096*64
#define OFF_RW2   536576     // + 4096*2

#define KSPLIT 4

// Scratch buffers
__device__ float g_xbuf[(size_t)NN * XPAD];             // aggregated features [N][XPAD]
__device__ float g_Wt[(size_t)DGRU * XPAD];             // router_W transposed [col][k], zero-padded
__device__ float g_part[(size_t)KSPLIT * NN * DGRU];    // router partial sums

// packed fp32x2 FMA (even/odd-k partial sums)
__device__ __forceinline__ void fma2(unsigned long long &d,
                                     unsigned long long a,
                                     unsigned long long b) {
    asm("fma.rn.f32x2 %0, %1, %2, %0;" : "+l"(d) : "l"(a), "l"(b));
}

// ---------------------------------------------------------------------------
// Kernel 1: per-stock aggregation (HBM-bound streaming) + W transpose
// (identical to the proven R3 version: 97us @ 83% DRAM)
// ---------------------------------------------------------------------------
__global__ void __launch_bounds__(256) agg_kernel(
    const float* __restrict__ price,   // [N,T,D]
    const float* __restrict__ news,    // [N,T,NEWS]
    const float* __restrict__ mask,    // [N,T]
    const float* __restrict__ router_W) // [1182,128]
{
    const int n = blockIdx.x;
    const int tid = threadIdx.x;
    __shared__ float sm[TT];
    __shared__ float sdenom;

    // W transpose side job (first 128 blocks) — overlapped with streaming
    if (n < DGRU) {
        for (int k = tid; k < XPAD; k += 256) {
            g_Wt[(size_t)n * XPAD + k] =
                (k < XDIM) ? router_W[(size_t)k * DGRU + n] : 0.f;
        }
    }

    if (tid < TT) {
        float mv = mask[(size_t)n * TT + tid];
        sm[tid] = mv;
        float s = mv;
        #pragma unroll
        for (int o = 16; o > 0; o >>= 1) s += __shfl_xor_sync(0xffffffffu, s, o);
        if (tid == 0) sdenom = fmaxf(s, 1e-6f);
    }
    __syncthreads();
    const float inv_denom = 1.0f / sdenom;

    // news: each thread owns 4 contiguous dims (one float4)
    const float4* news4 = (const float4*)(news + (size_t)n * TT * NEWS);
    float4 acc = make_float4(0.f, 0.f, 0.f, 0.f);
    #pragma unroll 8
    for (int t = 0; t < TT; t++) {
        float4 v = news4[t * (NEWS / 4) + tid];
        float mt = sm[t];
        acc.x += mt * v.x; acc.y += mt * v.y;
        acc.z += mt * v.z; acc.w += mt * v.w;
    }
    float* xb = g_xbuf + (size_t)n * XPAD;
    xb[DD + 4 * tid + 0] = acc.x * inv_denom;
    xb[DD + 4 * tid + 1] = acc.y * inv_denom;
    xb[DD + 4 * tid + 2] = acc.z * inv_denom;
    xb[DD + 4 * tid + 3] = acc.w * inv_denom;

    // price
    if (tid < DD) {
        float a = 0.f;
        const float* p = price + (size_t)n * TT * DD + tid;
        #pragma unroll 8
        for (int t = 0; t < TT; t++) a += p[t * DD];
        xb[tid] = a * (1.0f / TT);
    }
    if (tid == DD) { xb[XDIM] = 0.f; xb[XDIM + 1] = 0.f; }
}

// ---------------------------------------------------------------------------
// Kernel 2: router GEMM partials  g_part[q] = X @ W (k-range q)
// grid = 1024 blocks (128 stock tiles x 2 col halves x 4 k-splits), 256 thr.
// Same inner loop as the R3 router; K = 37 chunks of 32 split 10/9/9/9.
// bias + tanh + reduction moved into tail_kernel.
// ---------------------------------------------------------------------------
#define SB2 32
#define CB  64
#define KC2 32
#define XSTR 36    // padded smem row stride (floats)

__global__ void __launch_bounds__(256) router_kernel(void)
{
    const int q  = blockIdx.x & 3;           // k-split
    const int bc = (blockIdx.x >> 2) & 1;    // col half
    const int bs = blockIdx.x >> 3;          // stock tile
    const int s0 = bs * SB2;
    const int c0 = bc * CB;
    const int tid = threadIdx.x;

    // chunk range for this k-split: 37 chunks -> 10,9,9,9
    const int cbeg = (q == 0) ? 0 : (10 + (q - 1) * 9);
    const int cend = cbeg + ((q == 0) ? 10 : 9);
    const int kb0 = cbeg * KC2;
    const int kb1 = cend * KC2;

    __shared__ float Xs[SB2 * XSTR];   // [stock][k]
    __shared__ float Ws[CB  * XSTR];   // [col][k]

    const int sg = tid >> 5;           // warp id = stock group (4 stocks)
    const int cg = tid & 31;           // lane = col group {cg, cg+32}

    // staging indices (thread loads 1 X float4 + 2 W float4 per chunk)
    const int sA = tid >> 3;           // 0..31
    const int kA = (tid & 7) * 4;      // 0..28
    const float* xsrc = g_xbuf + (size_t)(s0 + sA) * XPAD + kA;
    const float* wsrc0 = g_Wt + (size_t)(c0 + sA) * XPAD + kA;
    const float* wsrc1 = g_Wt + (size_t)(c0 + 32 + sA) * XPAD + kA;

    unsigned long long acc[4][2];
    #pragma unroll
    for (int i = 0; i < 4; i++) { acc[i][0] = 0ull; acc[i][1] = 0ull; }

    float4 px  = *(const float4*)(xsrc  + kb0);
    float4 pw0 = *(const float4*)(wsrc0 + kb0);
    float4 pw1 = *(const float4*)(wsrc1 + kb0);

    for (int kc = kb0; kc < kb1; kc += KC2) {
        *(float4*)&Xs[sA * XSTR + kA]        = px;
        *(float4*)&Ws[sA * XSTR + kA]        = pw0;
        *(float4*)&Ws[(32 + sA) * XSTR + kA] = pw1;
        __syncthreads();

        int kn = kc + KC2;
        if (kn < kb1) {
            px  = *(const float4*)(xsrc  + kn);
            pw0 = *(const float4*)(wsrc0 + kn);
            pw1 = *(const float4*)(wsrc1 + kn);
        }

        #pragma unroll
        for (int kk = 0; kk < KC2; kk += 4) {
            ulonglong2 w0 = *(ulonglong2*)&Ws[cg * XSTR + kk];
            ulonglong2 w1 = *(ulonglong2*)&Ws[(cg + 32) * XSTR + kk];
            #pragma unroll
            for (int i = 0; i < 4; i++) {
                ulonglong2 x = *(ulonglong2*)&Xs[(sg * 4 + i) * XSTR + kk];
                fma2(acc[i][0], x.x, w0.x);
                fma2(acc[i][0], x.y, w0.y);
                fma2(acc[i][1], x.x, w1.x);
                fma2(acc[i][1], x.y, w1.y);
            }
        }
        __syncthreads();
    }

    // epilogue: combine even/odd partials, write raw partial sums
    float* pq = g_part + (size_t)q * NN * DGRU;
    #pragma unroll
    for (int i = 0; i < 4; i++) {
        const int s = s0 + sg * 4 + i;
        float v0 = __uint_as_float((unsigned)acc[i][0]) +
                   __uint_as_float((unsigned)(acc[i][0] >> 32));
        float v1 = __uint_as_float((unsigned)acc[i][1]) +
                   __uint_as_float((unsigned)(acc[i][1] >> 32));
        pq[(size_t)s * DGRU + c0 + cg]      = v0;
        pq[(size_t)s * DGRU + c0 + cg + 32] = v1;
    }
}

// ---------------------------------------------------------------------------
// Kernel 3: reduce+tanh + gate + top2/softmax + expert/attention + outputs
// grid = 256 blocks, 16 stocks per block, 256 threads.
// ---------------------------------------------------------------------------
#define SB3 16
#define HSTR 132   // padded Hs row stride

__global__ void __launch_bounds__(256) tail_kernel(
    const float* __restrict__ router_b,  // [128]
    const float* __restrict__ gate_W,    // [128,64]
    const float* __restrict__ gate_b,    // [64]
    const float* __restrict__ expert_W,  // [8,8,64]
    const float* __restrict__ expert_b,  // [8,8]
    const float* __restrict__ wq, const float* __restrict__ wq_b,
    const float* __restrict__ wk, const float* __restrict__ wk_b,
    const float* __restrict__ wv, const float* __restrict__ wv_b,
    const float* __restrict__ wo, const float* __restrict__ wo_b,
    float* __restrict__ out)
{
    const int s0 = blockIdx.x * SB3;
    const int tid = threadIdx.x;

    __shared__ float Hs[SB3 * HSTR];   // tanh(router) rows, padded
    __shared__ float Hid[SB3 * HID];
    __shared__ float Out[SB3 * HID];
    __shared__ int   Si1[SB3], Si2[SB3];
    __shared__ float Sw1[SB3], Sw2[SB3];

    // reduce partials + bias + tanh: 16 x 128 floats = 512 float4, 2/thread
    #pragma unroll
    for (int i = 0; i < 2; i++) {
        int idx = i * 256 + tid;
        int s = idx >> 5, kq = (idx & 31) * 4;
        size_t off = (size_t)(s0 + s) * DGRU + kq;
        float4 a0 = *(const float4*)&g_part[off];
        float4 a1 = *(const float4*)&g_part[(size_t)1 * NN * DGRU + off];
        float4 a2 = *(const float4*)&g_part[(size_t)2 * NN * DGRU + off];
        float4 a3 = *(const float4*)&g_part[(size_t)3 * NN * DGRU + off];
        float4 b  = *(const float4*)&router_b[kq];
        float4 r;
        r.x = tanhf(a0.x + a1.x + a2.x + a3.x + b.x);
        r.y = tanhf(a0.y + a1.y + a2.y + a3.y + b.y);
        r.z = tanhf(a0.z + a1.z + a2.z + a3.z + b.z);
        r.w = tanhf(a0.w + a1.w + a2.w + a3.w + b.w);
        *(float4*)&Hs[s * HSTR + kq] = r;
    }
    __syncthreads();

    // Gate: thread = (stock tid>>4, 4 cols)
    {
        int s  = tid >> 4;
        int cgp = tid & 15;
        float ga0 = gate_b[cgp * 4 + 0];
        float ga1 = gate_b[cgp * 4 + 1];
        float ga2 = gate_b[cgp * 4 + 2];
        float ga3 = gate_b[cgp * 4 + 3];
        #pragma unroll 8
        for (int j = 0; j < DGRU; j++) {
            float hv = Hs[s * HSTR + j];
            float4 w = __ldg((const float4*)&gate_W[j * HID + cgp * 4]);
            ga0 += hv * w.x; ga1 += hv * w.y; ga2 += hv * w.z; ga3 += hv * w.w;
        }
        Hid[s * HID + cgp * 4 + 0] = ga0;
        Hid[s * HID + cgp * 4 + 1] = ga1;
        Hid[s * HID + cgp * 4 + 2] = ga2;
        Hid[s * HID + cgp * 4 + 3] = ga3;
    }
    __syncthreads();

    // Top-2 + softmax, thread per stock
    if (tid < SB3) {
        int s = tid;
        float best1 = -3.4e38f; int i1 = 0;
        for (int c = 0; c < HID; c++) {
            float v = Hid[s * HID + c];
            if (v > best1) { best1 = v; i1 = c; }
        }
        float best2 = -3.4e38f; int i2 = 0;
        for (int c = 0; c < HID; c++) {
            if (c == i1) continue;
            float v = Hid[s * HID + c];
            if (v > best2) { best2 = v; i2 = c; }
        }
        float e2 = expf(best2 - best1);
        float r = 1.0f / (1.0f + e2);
        Si1[s] = i1; Si2[s] = i2;
        Sw1[s] = r;  Sw2[s] = e2 * r;
    }

    // Expert + attention: thread = (stock, group), 128 active threads
    if (tid < SB3 * GG) {
        int s = tid >> 3;
        int g = tid & 7;
        float eo[EE];
        #pragma unroll
        for (int e = 0; e < EE; e++) {
            float a = expert_b[g * EE + e];
            const float4* wr = (const float4*)&expert_W[((size_t)(g * EE + e)) * HID];
            const float4* hr = (const float4*)&Hid[s * HID];
            #pragma unroll
            for (int h4 = 0; h4 < HID / 4; h4++) {
                float4 w = wr[h4];
                float4 h = hr[h4];
                a += w.x * h.x + w.y * h.y + w.z * h.z + w.w * h.w;
            }
            eo[e] = a;
        }
        float q[EE], k[EE], v[EE];
        #pragma unroll
        for (int f = 0; f < EE; f++) {
            float aq = wq_b[g * EE + f];
            float ak = wk_b[g * EE + f];
            float av = wv_b[g * EE + f];
            #pragma unroll
            for (int e = 0; e < EE; e++) {
                aq += eo[e] * wq[(g * EE + f) * EE + e];
                ak += eo[e] * wk[(g * EE + f) * EE + e];
                av += eo[e] * wv[(g * EE + f) * EE + e];
            }
            q[f] = aq; k[f] = ak; v[f] = av;
        }
        const float isq = 0.70710678118654752f;
        float att[EE];
        #pragma unroll
        for (int d = 0; d < 2; d++) {
            float sc0 = 0.f, sc1 = 0.f;
            #pragma unroll
            for (int h = 0; h < HH; h++) {
                float qv = q[h * 2 + d];
                sc0 += qv * k[h * 2 + 0];
                sc1 += qv * k[h * 2 + 1];
            }
            sc0 *= isq; sc1 *= isq;
            float mx = fmaxf(sc0, sc1);
            float p0 = expf(sc0 - mx), p1 = expf(sc1 - mx);
            float rn = 1.0f / (p0 + p1);
            p0 *= rn; p1 *= rn;
            #pragma unroll
            for (int h = 0; h < HH; h++)
                att[h * 2 + d] = p0 * v[h * 2 + 0] + p1 * v[h * 2 + 1];
        }
        #pragma unroll
        for (int f = 0; f < EE; f++) {
            float a = wo_b[g * EE + f];
            #pragma unroll
            for (int e = 0; e < EE; e++)
                a += att[e] * wo[(g * EE + f) * EE + e];
            Out[s * HID + g * EE + f] = a;
        }
    }
    __syncthreads();

    // predictions + topk
    if (tid < SB3) {
        int s = tid;
        int i1 = Si1[s], i2 = Si2[s];
        float pred = Sw1[s] * Out[s * HID + i1] + Sw2[s] * Out[s * HID + i2];
        out[OFF_PRED + s0 + s] = pred;
        out[OFF_TOPK + (size_t)(s0 + s) * 2 + 0] = (float)i1;
        out[OFF_TOPK + (size_t)(s0 + s) * 2 + 1] = (float)i2;
    }

    // hidden + routing_weights (x2): 16 stocks x 64 cols = 256 float4
    {
        int s  = tid >> 4;
        int c  = (tid & 15) * 4;
        float4 hv = *(float4*)&Hid[s * HID + c];
        *(float4*)&out[OFF_HID + (size_t)(s0 + s) * HID + c] = hv;

        int i1 = Si1[s], i2 = Si2[s];
        float w1 = Sw1[s], w2 = Sw2[s];
        float4 rw;
        rw.x = (c + 0 == i1) ? w1 : (c + 0 == i2) ? w2 : 0.f;
        rw.y = (c + 1 == i1) ? w1 : (c + 1 == i2) ? w2 : 0.f;
        rw.z = (c + 2 == i1) ? w1 : (c + 2 == i2) ? w2 : 0.f;
        rw.w = (c + 3 == i1) ? w1 : (c + 3 == i2) ? w2 : 0.f;
        *(float4*)&out[OFF_RW1 + (size_t)(s0 + s) * HID + c] = rw;
        *(float4*)&out[OFF_RW2 + (size_t)(s0 + s) * HID + c] = rw;
    }
}

// ---------------------------------------------------------------------------
extern "C" void kernel_launch(void* const* d_in, const int* in_sizes, int n_in,
                              void* d_out, int out_size) {
    const float* price    = (const float*)d_in[0];
    const float* news     = (const float*)d_in[1];
    const float* mask     = (const float*)d_in[2];
    const float* router_W = (const float*)d_in[3];
    const float* router_b = (const float*)d_in[4];
    const float* gate_W   = (const float*)d_in[5];
    const float* gate_b   = (const float*)d_in[6];
    const float* expert_W = (const float*)d_in[7];
    const float* expert_b = (const float*)d_in[8];
    const float* wq   = (const float*)d_in[9];
    const float* wq_b = (const float*)d_in[10];
    const float* wk   = (const float*)d_in[11];
    const float* wk_b = (const float*)d_in[12];
    const float* wv   = (const float*)d_in[13];
    const float* wv_b = (const float*)d_in[14];
    const float* wo   = (const float*)d_in[15];
    const float* wo_b = (const float*)d_in[16];
    float* out = (float*)d_out;

    agg_kernel<<<NN, 256>>>(price, news, mask, router_W);
    router_kernel<<<(NN / SB2) * 2 * KSPLIT, 256>>>();
    tail_kernel<<<NN / SB3, 256>>>(router_b, gate_W, gate_b, expert_W, expert_b,
                                   wq, wq_b, wk, wk_b, wv, wv_b, wo, wo_b,
                                   out);
}

// round 15
// speedup vs baseline: 2.0295x; 1.0993x over previous
#include <cuda_runtime.h>
#include <cuda_bf16.h>
#include <stdint.h>
#include <math.h>

// Problem constants
#define NN 4096
#define TT 32
#define DD 158
#define NEWS 1024
#define DGRU 128
#define GG 8
#define EE 8
#define HH 4
#define HID 64          // G*E
#define XDIM 1182       // D + NEWS
#define XPAD 1184       // padded to multiple of 32

// Output layout (float32, concat of tuple)
#define OFF_PRED  0
#define OFF_RW1   4096
#define OFF_HID   266240     // 4096 + 4096*64
#define OFF_TOPK  528384     // + 4096*64
#define OFF_RW2   536576     // + 4096*2

#define KSPLIT 4

// Scratch buffers (bf16 hi/lo split operands for the tensor-core router)
__device__ __nv_bfloat16 g_xh[(size_t)NN * XPAD];
__device__ __nv_bfloat16 g_xl[(size_t)NN * XPAD];
__device__ __nv_bfloat16 g_Wth[(size_t)DGRU * XPAD];   // W^T [col][k]
__device__ __nv_bfloat16 g_Wtl[(size_t)DGRU * XPAD];
__device__ float g_part[(size_t)KSPLIT * NN * DGRU];   // router partial sums

__device__ __forceinline__ void bf16_split(float v, __nv_bfloat16 &hi, __nv_bfloat16 &lo) {
    hi = __float2bfloat16(v);
    lo = __float2bfloat16(v - __bfloat162float(hi));
}

// ---------------------------------------------------------------------------
// Kernel 1: per-stock aggregation (HBM-bound streaming) + W split/transpose
// ---------------------------------------------------------------------------
__global__ void __launch_bounds__(256) agg_kernel(
    const float* __restrict__ price,   // [N,T,D]
    const float* __restrict__ news,    // [N,T,NEWS]
    const float* __restrict__ mask,    // [N,T]
    const float* __restrict__ router_W) // [1182,128]
{
    const int n = blockIdx.x;
    const int tid = threadIdx.x;
    __shared__ float sm[TT];
    __shared__ float sdenom;

    // W transpose + bf16 split side job (first 128 blocks)
    if (n < DGRU) {
        for (int k = tid; k < XPAD; k += 256) {
            float w = (k < XDIM) ? router_W[(size_t)k * DGRU + n] : 0.f;
            __nv_bfloat16 hi, lo;
            bf16_split(w, hi, lo);
            g_Wth[(size_t)n * XPAD + k] = hi;
            g_Wtl[(size_t)n * XPAD + k] = lo;
        }
    }

    if (tid < TT) {
        float mv = mask[(size_t)n * TT + tid];
        sm[tid] = mv;
        float s = mv;
        #pragma unroll
        for (int o = 16; o > 0; o >>= 1) s += __shfl_xor_sync(0xffffffffu, s, o);
        if (tid == 0) sdenom = fmaxf(s, 1e-6f);
    }
    __syncthreads();
    const float inv_denom = 1.0f / sdenom;

    // news: each thread owns 4 contiguous dims (one float4)
    const float4* news4 = (const float4*)(news + (size_t)n * TT * NEWS);
    float4 acc = make_float4(0.f, 0.f, 0.f, 0.f);
    #pragma unroll 8
    for (int t = 0; t < TT; t++) {
        float4 v = news4[t * (NEWS / 4) + tid];
        float mt = sm[t];
        acc.x += mt * v.x; acc.y += mt * v.y;
        acc.z += mt * v.z; acc.w += mt * v.w;
    }
    {
        float v[4] = { acc.x * inv_denom, acc.y * inv_denom,
                       acc.z * inv_denom, acc.w * inv_denom };
        size_t base = (size_t)n * XPAD + DD + 4 * tid;
        #pragma unroll
        for (int j = 0; j < 4; j++) {
            __nv_bfloat16 hi, lo;
            bf16_split(v[j], hi, lo);
            g_xh[base + j] = hi;
            g_xl[base + j] = lo;
        }
    }

    // price
    if (tid < DD) {
        float a = 0.f;
        const float* p = price + (size_t)n * TT * DD + tid;
        #pragma unroll 8
        for (int t = 0; t < TT; t++) a += p[t * DD];
        float v = a * (1.0f / TT);
        __nv_bfloat16 hi, lo;
        bf16_split(v, hi, lo);
        g_xh[(size_t)n * XPAD + tid] = hi;
        g_xl[(size_t)n * XPAD + tid] = lo;
    }
    if (tid == DD) {
        __nv_bfloat16 z = __float2bfloat16(0.f);
        g_xh[(size_t)n * XPAD + XDIM] = z; g_xh[(size_t)n * XPAD + XDIM + 1] = z;
        g_xl[(size_t)n * XPAD + XDIM] = z; g_xl[(size_t)n * XPAD + XDIM + 1] = z;
    }
}

// ---------------------------------------------------------------------------
// Kernel 2: tensor-core router GEMM partials (3x bf16 split emulation)
// g_part[q] = X @ W (k-range q), fp32 accum via mma.sync.m16n8k16.bf16
// grid = 128 stock tiles x 4 k-splits = 512 blocks, 256 threads (8 warps).
// Block tile M=32 x N=128. Warp: 16 x 32 (4 n-tiles of 8).
// ---------------------------------------------------------------------------
#define ASTR 40    // smem row strides (halves) - 80B: 8 ldmatrix rows hit
#define BSTR 40    // 8 distinct bank groups -> conflict-free

__device__ __forceinline__ void ldsm4(uint32_t* r, uint32_t addr) {
    asm volatile("ldmatrix.sync.aligned.m8n8.x4.shared.b16 {%0,%1,%2,%3}, [%4];\n"
        : "=r"(r[0]), "=r"(r[1]), "=r"(r[2]), "=r"(r[3]) : "r"(addr));
}
__device__ __forceinline__ void mma_bf16(float* d, const uint32_t* a,
                                         uint32_t b0, uint32_t b1) {
    asm volatile(
        "mma.sync.aligned.m16n8k16.row.col.f32.bf16.bf16.f32 "
        "{%0,%1,%2,%3}, {%4,%5,%6,%7}, {%8,%9}, {%0,%1,%2,%3};\n"
        : "+f"(d[0]), "+f"(d[1]), "+f"(d[2]), "+f"(d[3])
        : "r"(a[0]), "r"(a[1]), "r"(a[2]), "r"(a[3]), "r"(b0), "r"(b1));
}

__global__ void __launch_bounds__(256) router_mma(void)
{
    const int q  = blockIdx.x & 3;           // k-split
    const int bs = blockIdx.x >> 2;          // stock tile
    const int s0 = bs * 32;
    const int tid = threadIdx.x;
    const int wid = tid >> 5, lane = tid & 31;
    const int wm = wid & 1, wn = wid >> 1;   // warp = (m-half, n-quarter)
    const int mbase = wm * 16;
    const int nb0 = wn * 32;

    __shared__ __align__(16) __nv_bfloat16 Ah[32 * ASTR], Al[32 * ASTR];
    __shared__ __align__(16) __nv_bfloat16 Bh[128 * BSTR], Bl[128 * BSTR];

    // chunk range: 37 chunks of 32 -> 10/9/9/9
    const int cbeg = (q == 0) ? 0 : 10 + (q - 1) * 9;
    const int nch  = (q == 0) ? 10 : 9;

    float acc[4][4];
    #pragma unroll
    for (int i = 0; i < 4; i++)
        #pragma unroll
        for (int j = 0; j < 4; j++) acc[i][j] = 0.f;

    // ldmatrix per-lane addresses (tile order matches mma fragment order)
    const int g  = lane >> 3, lr = lane & 7;
    const int a_row  = mbase + lr + (g & 1) * 8;      // tiles: m0k0,m8k0,m0k8,m8k8
    const int a_koff = (g >> 1) * 8;
    const int b_row  = lr + (g >> 1) * 8;             // tiles: n0k0,n0k8,n8k0,n8k8
    const int b_koff = (g & 1) * 8;

    const uint32_t aAh = (uint32_t)__cvta_generic_to_shared(&Ah[a_row * ASTR + a_koff]);
    const uint32_t aAl = (uint32_t)__cvta_generic_to_shared(&Al[a_row * ASTR + a_koff]);
    const uint32_t aBh0 = (uint32_t)__cvta_generic_to_shared(&Bh[(nb0 + b_row) * BSTR + b_koff]);
    const uint32_t aBh1 = (uint32_t)__cvta_generic_to_shared(&Bh[(nb0 + 16 + b_row) * BSTR + b_koff]);
    const uint32_t aBl0 = (uint32_t)__cvta_generic_to_shared(&Bl[(nb0 + b_row) * BSTR + b_koff]);
    const uint32_t aBl1 = (uint32_t)__cvta_generic_to_shared(&Bl[(nb0 + 16 + b_row) * BSTR + b_koff]);

    // staging indices
    const int ar = tid >> 2, ao = (tid & 3) * 8;      // A: tid<128, 8 halves each
    const int br = tid >> 1, bo = (tid & 1) * 16;     // B: 16 halves each (2x uint4)

    for (int c = 0; c < nch; c++) {
        const int k0 = (cbeg + c) * 32;
        if (tid < 128) {
            *(uint4*)&Ah[ar * ASTR + ao] =
                *(const uint4*)&g_xh[(size_t)(s0 + ar) * XPAD + k0 + ao];
            *(uint4*)&Al[ar * ASTR + ao] =
                *(const uint4*)&g_xl[(size_t)(s0 + ar) * XPAD + k0 + ao];
        }
        {
            const __nv_bfloat16* sh = &g_Wth[(size_t)br * XPAD + k0 + bo];
            const __nv_bfloat16* sl = &g_Wtl[(size_t)br * XPAD + k0 + bo];
            *(uint4*)&Bh[br * BSTR + bo]     = *(const uint4*)sh;
            *(uint4*)&Bh[br * BSTR + bo + 8] = *(const uint4*)(sh + 8);
            *(uint4*)&Bl[br * BSTR + bo]     = *(const uint4*)sl;
            *(uint4*)&Bl[br * BSTR + bo + 8] = *(const uint4*)(sl + 8);
        }
        __syncthreads();

        #pragma unroll
        for (int kk = 0; kk < 32; kk += 16) {
            uint32_t ah[4], al[4], bh[8], bl[8];
            const uint32_t kb = kk * 2;   // bytes
            ldsm4(ah, aAh + kb);
            ldsm4(al, aAl + kb);
            ldsm4(bh + 0, aBh0 + kb);
            ldsm4(bh + 4, aBh1 + kb);
            ldsm4(bl + 0, aBl0 + kb);
            ldsm4(bl + 4, aBl1 + kb);
            #pragma unroll
            for (int nt = 0; nt < 4; nt++) {
                mma_bf16(acc[nt], ah, bh[nt * 2], bh[nt * 2 + 1]);  // xh*wh
                mma_bf16(acc[nt], ah, bl[nt * 2], bl[nt * 2 + 1]);  // xh*wl
                mma_bf16(acc[nt], al, bh[nt * 2], bh[nt * 2 + 1]);  // xl*wh
            }
        }
        __syncthreads();
    }

    // epilogue: write fp32 partials (C frag: rows T/4 & T/4+8, cols 2(T%4)+{0,1})
    float* pq = g_part + (size_t)q * NN * DGRU;
    const int er = s0 + mbase + (lane >> 2);
    const int ec = (lane & 3) * 2;
    #pragma unroll
    for (int nt = 0; nt < 4; nt++) {
        const int col = nb0 + nt * 8 + ec;
        *(float2*)&pq[(size_t)er * DGRU + col]       = make_float2(acc[nt][0], acc[nt][1]);
        *(float2*)&pq[(size_t)(er + 8) * DGRU + col] = make_float2(acc[nt][2], acc[nt][3]);
    }
}

// ---------------------------------------------------------------------------
// Kernel 3: reduce+tanh + gate + top2/softmax + expert/attention + outputs
// grid = 256 blocks, 16 stocks per block, 256 threads. (proven R10 version)
// ---------------------------------------------------------------------------
#define SB3 16
#define HSTR 132   // padded Hs row stride

__global__ void __launch_bounds__(256) tail_kernel(
    const float* __restrict__ router_b,  // [128]
    const float* __restrict__ gate_W,    // [128,64]
    const float* __restrict__ gate_b,    // [64]
    const float* __restrict__ expert_W,  // [8,8,64]
    const float* __restrict__ expert_b,  // [8,8]
    const float* __restrict__ wq, const float* __restrict__ wq_b,
    const float* __restrict__ wk, const float* __restrict__ wk_b,
    const float* __restrict__ wv, const float* __restrict__ wv_b,
    const float* __restrict__ wo, const float* __restrict__ wo_b,
    float* __restrict__ out)
{
    const int s0 = blockIdx.x * SB3;
    const int tid = threadIdx.x;

    __shared__ float Hs[SB3 * HSTR];   // tanh(router) rows, padded
    __shared__ float Hid[SB3 * HID];
    __shared__ float Out[SB3 * HID];
    __shared__ int   Si1[SB3], Si2[SB3];
    __shared__ float Sw1[SB3], Sw2[SB3];

    // reduce partials + bias + tanh
    #pragma unroll
    for (int i = 0; i < 2; i++) {
        int idx = i * 256 + tid;
        int s = idx >> 5, kq = (idx & 31) * 4;
        size_t off = (size_t)(s0 + s) * DGRU + kq;
        float4 a0 = *(const float4*)&g_part[off];
        float4 a1 = *(const float4*)&g_part[(size_t)1 * NN * DGRU + off];
        float4 a2 = *(const float4*)&g_part[(size_t)2 * NN * DGRU + off];
        float4 a3 = *(const float4*)&g_part[(size_t)3 * NN * DGRU + off];
        float4 b  = *(const float4*)&router_b[kq];
        float4 r;
        r.x = tanhf(a0.x + a1.x + a2.x + a3.x + b.x);
        r.y = tanhf(a0.y + a1.y + a2.y + a3.y + b.y);
        r.z = tanhf(a0.z + a1.z + a2.z + a3.z + b.z);
        r.w = tanhf(a0.w + a1.w + a2.w + a3.w + b.w);
        *(float4*)&Hs[s * HSTR + kq] = r;
    }
    __syncthreads();

    // Gate
    {
        int s  = tid >> 4;
        int cgp = tid & 15;
        float ga0 = gate_b[cgp * 4 + 0];
        float ga1 = gate_b[cgp * 4 + 1];
        float ga2 = gate_b[cgp * 4 + 2];
        float ga3 = gate_b[cgp * 4 + 3];
        #pragma unroll 8
        for (int j = 0; j < DGRU; j++) {
            float hv = Hs[s * HSTR + j];
            float4 w = __ldg((const float4*)&gate_W[j * HID + cgp * 4]);
            ga0 += hv * w.x; ga1 += hv * w.y; ga2 += hv * w.z; ga3 += hv * w.w;
        }
        Hid[s * HID + cgp * 4 + 0] = ga0;
        Hid[s * HID + cgp * 4 + 1] = ga1;
        Hid[s * HID + cgp * 4 + 2] = ga2;
        Hid[s * HID + cgp * 4 + 3] = ga3;
    }
    __syncthreads();

    // Top-2 + softmax
    if (tid < SB3) {
        int s = tid;
        float best1 = -3.4e38f; int i1 = 0;
        for (int c = 0; c < HID; c++) {
            float v = Hid[s * HID + c];
            if (v > best1) { best1 = v; i1 = c; }
        }
        float best2 = -3.4e38f; int i2 = 0;
        for (int c = 0; c < HID; c++) {
            if (c == i1) continue;
            float v = Hid[s * HID + c];
            if (v > best2) { best2 = v; i2 = c; }
        }
        float e2 = expf(best2 - best1);
        float r = 1.0f / (1.0f + e2);
        Si1[s] = i1; Si2[s] = i2;
        Sw1[s] = r;  Sw2[s] = e2 * r;
    }

    // Expert + attention
    if (tid < SB3 * GG) {
        int s = tid >> 3;
        int g = tid & 7;
        float eo[EE];
        #pragma unroll
        for (int e = 0; e < EE; e++) {
            float a = expert_b[g * EE + e];
            const float4* wr = (const float4*)&expert_W[((size_t)(g * EE + e)) * HID];
            const float4* hr = (const float4*)&Hid[s * HID];
            #pragma unroll
            for (int h4 = 0; h4 < HID / 4; h4++) {
                float4 w = wr[h4];
                float4 h = hr[h4];
                a += w.x * h.x + w.y * h.y + w.z * h.z + w.w * h.w;
            }
            eo[e] = a;
        }
        float qv[EE], kv[EE], vv[EE];
        #pragma unroll
        for (int f = 0; f < EE; f++) {
            float aq = wq_b[g * EE + f];
            float ak = wk_b[g * EE + f];
            float av = wv_b[g * EE + f];
            #pragma unroll
            for (int e = 0; e < EE; e++) {
                aq += eo[e] * wq[(g * EE + f) * EE + e];
                ak += eo[e] * wk[(g * EE + f) * EE + e];
                av += eo[e] * wv[(g * EE + f) * EE + e];
            }
            qv[f] = aq; kv[f] = ak; vv[f] = av;
        }
        const float isq = 0.70710678118654752f;
        float att[EE];
        #pragma unroll
        for (int d = 0; d < 2; d++) {
            float sc0 = 0.f, sc1 = 0.f;
            #pragma unroll
            for (int h = 0; h < HH; h++) {
                float qq = qv[h * 2 + d];
                sc0 += qq * kv[h * 2 + 0];
                sc1 += qq * kv[h * 2 + 1];
            }
            sc0 *= isq; sc1 *= isq;
            float mx = fmaxf(sc0, sc1);
            float p0 = expf(sc0 - mx), p1 = expf(sc1 - mx);
            float rn = 1.0f / (p0 + p1);
            p0 *= rn; p1 *= rn;
            #pragma unroll
            for (int h = 0; h < HH; h++)
                att[h * 2 + d] = p0 * vv[h * 2 + 0] + p1 * vv[h * 2 + 1];
        }
        #pragma unroll
        for (int f = 0; f < EE; f++) {
            float a = wo_b[g * EE + f];
            #pragma unroll
            for (int e = 0; e < EE; e++)
                a += att[e] * wo[(g * EE + f) * EE + e];
            Out[s * HID + g * EE + f] = a;
        }
    }
    __syncthreads();

    // predictions + topk
    if (tid < SB3) {
        int s = tid;
        int i1 = Si1[s], i2 = Si2[s];
        float pred = Sw1[s] * Out[s * HID + i1] + Sw2[s] * Out[s * HID + i2];
        out[OFF_PRED + s0 + s] = pred;
        out[OFF_TOPK + (size_t)(s0 + s) * 2 + 0] = (float)i1;
        out[OFF_TOPK + (size_t)(s0 + s) * 2 + 1] = (float)i2;
    }

    // hidden + routing_weights (x2)
    {
        int s  = tid >> 4;
        int c  = (tid & 15) * 4;
        float4 hv = *(float4*)&Hid[s * HID + c];
        *(float4*)&out[OFF_HID + (size_t)(s0 + s) * HID + c] = hv;

        int i1 = Si1[s], i2 = Si2[s];
        float w1 = Sw1[s], w2 = Sw2[s];
        float4 rw;
        rw.x = (c + 0 == i1) ? w1 : (c + 0 == i2) ? w2 : 0.f;
        rw.y = (c + 1 == i1) ? w1 : (c + 1 == i2) ? w2 : 0.f;
        rw.z = (c + 2 == i1) ? w1 : (c + 2 == i2) ? w2 : 0.f;
        rw.w = (c + 3 == i1) ? w1 : (c + 3 == i2) ? w2 : 0.f;
        *(float4*)&out[OFF_RW1 + (size_t)(s0 + s) * HID + c] = rw;
        *(float4*)&out[OFF_RW2 + (size_t)(s0 + s) * HID + c] = rw;
    }
}

// ---------------------------------------------------------------------------
extern "C" void kernel_launch(void* const* d_in, const int* in_sizes, int n_in,
                              void* d_out, int out_size) {
    const float* price    = (const float*)d_in[0];
    const float* news     = (const float*)d_in[1];
    const float* mask     = (const float*)d_in[2];
    const float* router_W = (const float*)d_in[3];
    const float* router_b = (const float*)d_in[4];
    const float* gate_W   = (const float*)d_in[5];
    const float* gate_b   = (const float*)d_in[6];
    const float* expert_W = (const float*)d_in[7];
    const float* expert_b = (const float*)d_in[8];
    const float* wq   = (const float*)d_in[9];
    const float* wq_b = (const float*)d_in[10];
    const float* wk   = (const float*)d_in[11];
    const float* wk_b = (const float*)d_in[12];
    const float* wv   = (const float*)d_in[13];
    const float* wv_b = (const float*)d_in[14];
    const float* wo   = (const float*)d_in[15];
    const float* wo_b = (const float*)d_in[16];
    float* out = (float*)d_out;

    agg_kernel<<<NN, 256>>>(price, news, mask, router_W);
    router_mma<<<(NN / 32) * KSPLIT, 256>>>();
    tail_kernel<<<NN / SB3, 256>>>(router_b, gate_W, gate_b, expert_W, expert_b,
                                   wq, wq_b, wk, wk_b, wv, wv_b, wo, wo_b,
                                   out);
}